// round 13
// baseline (speedup 1.0000x reference)
#include <cuda_runtime.h>
#include <cstdint>
#include <math.h>

// CapsuleLayer: u_hat[b,c,r,o] = sum_i W[c,r,o,i]*x[b,r,i]; out = squash over o.
// B=256, C=10, R=1152, O=16, I=8.
//
// Block = (32 routes x 16 batches), 128 threads, loops over 5 capsule-pairs.
// Lane roles within each route's 4-lane group (op = tid&3):
//   op0: capsule cc,   outputs 0-7     op1: capsule cc,   outputs 8-15
//   op2: capsule cc+5, outputs 0-7     op3: capsule cc+5, outputs 8-15
// -> o-norm reduction = ONE shfl.xor(1) serving both capsules (was 4 shfls).
// x tile in smem (48B route stride, conflict-free 4-lane-broadcast LDS.128).
// W: 64 contiguous floats/thread in regs; f32x2 packed dots; single-MUFU squash.
// Grid 36x16 = 576 blocks (single wave).

#define NUM_CAPSULES 10
#define NUM_ROUTES   1152
#define IN_CH        8
#define OUT_CH       16
#define RT           32     // routes per block
#define BCHUNKS      16
#define BCHUNK_LEN   16     // 256 / BCHUNKS
#define RSTRIDE_F    12     // floats per route row in smem (48B, bank-swizzle)
#define CPAIR        5      // capsule pair stride (c, c+5)

__device__ __forceinline__ uint64_t f2mul(uint64_t a, uint64_t b)
{
    uint64_t d;
    asm("mul.rn.f32x2 %0, %1, %2;" : "=l"(d) : "l"(a), "l"(b));
    return d;
}
__device__ __forceinline__ uint64_t f2fma(uint64_t a, uint64_t b, uint64_t c)
{
    uint64_t d;
    asm("fma.rn.f32x2 %0, %1, %2, %3;" : "=l"(d) : "l"(a), "l"(b), "l"(c));
    return d;
}
__device__ __forceinline__ float f2hsum(uint64_t v)
{
    float lo, hi;
    asm("mov.b64 {%0, %1}, %2;" : "=f"(lo), "=f"(hi) : "l"(v));
    return lo + hi;
}

__device__ __forceinline__ float dot8p(const ulonglong2 wa, const ulonglong2 wb,
                                       const ulonglong2 xa, const ulonglong2 xb)
{
    uint64_t t = f2mul(wa.x, xa.x);
    t = f2fma(wa.y, xa.y, t);
    t = f2fma(wb.x, xb.x, t);
    t = f2fma(wb.y, xb.y, t);
    return f2hsum(t);
}

__global__ __launch_bounds__(128) void capsule_kernel(
    const float* __restrict__ x,   // [B, R, 8]
    const float* __restrict__ W,   // [C, R, 16, 8]
    float* __restrict__ out)       // [B, C, R, 16]
{
    __shared__ float x_s[BCHUNK_LEN * RT * RSTRIDE_F];   // 24 KB

    const int tid  = threadIdx.x;
    const int rr   = tid >> 2;          // 0..31 route within tile
    const int op   = tid & 3;           // lane role
    const int pair = op >> 1;           // 0 -> capsule cc, 1 -> capsule cc+5
    const int half = op & 1;            // 0 -> outputs 0-7, 1 -> outputs 8-15
    const int r0   = blockIdx.x * RT;
    const int r    = r0 + rr;
    const int b0   = blockIdx.y * BCHUNK_LEN;

    const size_t XB = (size_t)NUM_ROUTES * IN_CH;                   // x batch stride
    const size_t OB = (size_t)NUM_CAPSULES * NUM_ROUTES * OUT_CH;   // out batch stride

    // ---- Stage x tile: 16 b x 32 r x 2 float4, fully coalesced global reads. ----
#pragma unroll
    for (int it = 0; it < (BCHUNK_LEN * RT * 2) / 128; it++) {
        const int idx = it * 128 + tid;          // 0..1023
        const int bb  = idx >> 6;                // /64
        const int rem = idx & 63;
        const int rs  = rem >> 1;                // route within tile
        const int j   = rem & 1;                 // float4 half
        const float4 v = *reinterpret_cast<const float4*>(
            x + (size_t)(b0 + bb) * XB + (size_t)(r0 + rs) * IN_CH + j * 4);
        *reinterpret_cast<float4*>(
            x_s + bb * (RT * RSTRIDE_F) + rs * RSTRIDE_F + j * 4) = v;
    }
    __syncthreads();

    const float* xrow = x_s + rr * RSTRIDE_F;    // this thread-group's route

    const size_t w_step = (size_t)NUM_ROUTES * OUT_CH * IN_CH;      // per-capsule W stride

#pragma unroll 1
    for (int cc = 0; cc < CPAIR; cc++) {
        const int c_lane = cc + pair * CPAIR;    // this lane's capsule

        // This lane's 64 W floats (its 8 outputs x 8 inputs) -> 16 ulonglong2.
        const ulonglong2* Wg = reinterpret_cast<const ulonglong2*>(
            W + (size_t)c_lane * w_step
              + (((size_t)r) * OUT_CH + half * 8) * IN_CH);
        ulonglong2 w[16];
#pragma unroll
        for (int j = 0; j < 16; j++) w[j] = Wg[j];

        const size_t o_base = ((size_t)c_lane * NUM_ROUTES + r) * OUT_CH + half * 8;

#pragma unroll 2
        for (int bb = 0; bb < BCHUNK_LEN; bb++) {
            const ulonglong2 xa = *reinterpret_cast<const ulonglong2*>(
                xrow + bb * (RT * RSTRIDE_F));
            const ulonglong2 xb = *reinterpret_cast<const ulonglong2*>(
                xrow + bb * (RT * RSTRIDE_F) + 4);

            float u[8];
#pragma unroll
            for (int o = 0; o < 8; o++)
                u[o] = dot8p(w[2 * o], w[2 * o + 1], xa, xb);

            float sq = u[0] * u[0];
#pragma unroll
            for (int o = 1; o < 8; o++) sq = fmaf(u[o], u[o], sq);

            // One shfl completes BOTH capsules' 16-o norms:
            // op0<->op1 (capsule cc), op2<->op3 (capsule cc+5).
            sq += __shfl_xor_sync(0xFFFFFFFFu, sq, 1);

            // squash: scale = sq/(1+sq)/sqrt(sq+1e-9) = sq*rsqrt((sq+1e-9)*(1+sq)^2)
            const float opl   = 1.0f + sq;
            const float scale = sq * rsqrtf((sq + 1e-9f) * (opl * opl));

            float4* og = reinterpret_cast<float4*>(
                out + (size_t)(b0 + bb) * OB + o_base);
            og[0] = make_float4(u[0] * scale, u[1] * scale, u[2] * scale, u[3] * scale);
            og[1] = make_float4(u[4] * scale, u[5] * scale, u[6] * scale, u[7] * scale);
        }
    }
}

extern "C" void kernel_launch(void* const* d_in, const int* in_sizes, int n_in,
                              void* d_out, int out_size)
{
    const float* x = (const float*)d_in[0];   // [B, 1152, 8]
    const float* W = (const float*)d_in[1];   // [1, 10, 1152, 16, 8]
    float* out = (float*)d_out;               // [B, 10, 1152, 16]

    dim3 grid(NUM_ROUTES / RT, BCHUNKS);      // 36 x 16 = 576 blocks
    dim3 block(128);
    capsule_kernel<<<grid, block>>>(x, W, out);
}